// round 2
// baseline (speedup 1.0000x reference)
#include <cuda_runtime.h>
#include <stdint.h>

#define NMAX 33600
#define GMAX 128
#define CMAX 80
#define TPB 256
#define TK 10
#define EPSF 1e-7f
#define INF_F 100000.0f
#define BIG_F 100000000.0f
#define CRAD 2.5f
#define NWORDS ((NMAX + 31) / 32)

// ---- scratch as __device__ globals (allocation-free rule) ----
__device__ float    g_D[(size_t)CMAX * NMAX];     // (L - L1) class-major
__device__ float    g_L1[(size_t)CMAX * NMAX];    // L1 class-major
__device__ float    g_sumL1[NMAX];
__device__ float    g_iou[(size_t)GMAX * NMAX];   // raw IoU, gt-major
__device__ float    g_cost[(size_t)GMAX * NMAX];  // cost incl. +INF term, NOT valid-masked
__device__ unsigned g_valid[NWORDS];
__device__ int      g_cnt[NMAX];
__device__ int      g_mg[NMAX];

// monotone float->uint (ascending order preserved)
__device__ __forceinline__ unsigned fkey(float f) {
    unsigned u = __float_as_uint(f);
    return (u & 0x80000000u) ? ~u : (u | 0x80000000u);
}
__device__ __forceinline__ float unfkey(unsigned k) {
    unsigned u = (k & 0x80000000u) ? (k ^ 0x80000000u) : ~k;
    return __uint_as_float(u);
}

// ---------------- kA1: per-(c,n) log terms ----------------
__global__ void kA1(const float* __restrict__ ps, int N, int C) {
    int idx = blockIdx.x * blockDim.x + threadIdx.x;
    if (idx >= N * C) return;
    int c = idx / N;
    int n = idx - c * N;
    float p  = ps[(size_t)n * C + c];
    float L  = fmaxf(__logf(p), -100.f);
    float L1 = fmaxf(__logf(1.f - p), -100.f);
    g_D[idx]  = L - L1;
    g_L1[idx] = L1;
}

// ---------------- kA2: sum of L1 over classes ----------------
__global__ void kA2(int N, int C) {
    int n = blockIdx.x * blockDim.x + threadIdx.x;
    if (n >= N) return;
    float s = 0.f;
    for (int c = 0; c < C; c++) s += g_L1[(size_t)c * N + n];
    g_sumL1[n] = s;
}

// ---------------- init ----------------
__global__ void kInit(int N) {
    int i = blockIdx.x * blockDim.x + threadIdx.x;
    if (i < N) { g_cnt[i] = 0; g_mg[i] = 0x7fffffff; }
    if (i < NWORDS) g_valid[i] = 0u;
}

// -------- kB: pairwise flags + IoU + cost (raw) --------
__global__ void __launch_bounds__(TPB) kB(
    const float* __restrict__ priors, const float* __restrict__ dec,
    const float* __restrict__ gtb, const int* __restrict__ gtl,
    int N, int G)
{
    __shared__ float4 sg0[32];
    __shared__ float4 sg1[32];
    int tid = threadIdx.x;
    int g0 = blockIdx.y * 32;
    int gcnt = min(32, G - g0);
    if (tid < gcnt) {
        int g = g0 + tid;
        float x0 = gtb[4*g+0], y0 = gtb[4*g+1], x1 = gtb[4*g+2], y1 = gtb[4*g+3];
        sg0[tid] = make_float4(x0, y0, x1, y1);
        float gcx = (x0 + x1) * 0.5f, gcy = (y0 + y1) * 0.5f;
        float area = fmaxf(x1 - x0, 0.f) * fmaxf(y1 - y0, 0.f);
        sg1[tid] = make_float4(gcx, gcy, area, __int_as_float(gtl[g]));
    }
    __syncthreads();

    int n = blockIdx.x * blockDim.x + tid;
    bool active = (n < N);
    float px=0, py=0, a1=0, a2=0, b1=0, b2=0;
    float dx0=0, dy0=0, dx1=0, dy1=0, aa=0, sL1=0;
    if (active) {
        float4 pq = ((const float4*)priors)[n];
        px = pq.x; py = pq.y;
        a1 = px + CRAD * pq.z; a2 = px - CRAD * pq.z;
        b1 = py + CRAD * pq.w; b2 = py - CRAD * pq.w;
        float4 dq = ((const float4*)dec)[n];
        dx0 = dq.x; dy0 = dq.y; dx1 = dq.z; dy1 = dq.w;
        aa = fmaxf(dx1 - dx0, 0.f) * fmaxf(dy1 - dy0, 0.f);
        sL1 = g_sumL1[n];
    }
    bool vacc = false;
    #pragma unroll 4
    for (int gi = 0; gi < gcnt; gi++) {
        float4 q0 = sg0[gi];
        float4 q1 = sg1[gi];
        if (active) {
            int g = g0 + gi;
            float m1 = fminf(fminf(px - q0.x, py - q0.y), fminf(q0.z - px, q0.w - py));
            float m2 = fminf(fminf(a1 - q1.x, b1 - q1.y), fminf(q1.x - a2, q1.y - b2));
            bool ing = m1 > 0.f, inc = m2 > 0.f;
            vacc = vacc || ing || inc;
            float w = fmaxf(fminf(dx1, q0.z) - fmaxf(dx0, q0.x), 0.f);
            float h = fmaxf(fminf(dy1, q0.w) - fmaxf(dy0, q0.y), 0.f);
            float inter = w * h;
            float uni = fmaxf(aa + q1.z - inter, EPSF);
            float iou = __fdividef(inter, uni);
            int lbl = __float_as_int(q1.w);
            float cls = -g_D[(size_t)lbl * N + n] - sL1;
            float cost = cls - 3.0f * __logf(iou + EPSF);
            if (!(ing && inc)) cost += INF_F;
            g_iou [(size_t)g * N + n] = iou;
            g_cost[(size_t)g * N + n] = cost;
        }
    }
    unsigned m = __ballot_sync(0xffffffffu, vacc);
    if ((tid & 31) == 0 && active && m) atomicOr(&g_valid[n >> 5], m);
}

// -------- kTop: per-GT top-10 of iou (desc) then cost (asc) --------
template <bool MAXI>
__device__ void topk_pass(const float* __restrict__ col, int N, float maskval,
                          unsigned long long* sk, unsigned long long* swred,
                          unsigned long long* skeep)
{
    int tid = threadIdx.x;
    unsigned long long kept[TK];
    #pragma unroll
    for (int i = 0; i < TK; i++) kept[i] = ~0ULL;
    unsigned long long th = ~0ULL;
    for (int n = tid; n < N; n += TPB) {
        float v = col[n];
        if (!((g_valid[n >> 5] >> (n & 31)) & 1u)) v = maskval;
        unsigned fk = fkey(v);
        if (MAXI) fk = ~fk;
        unsigned long long key = ((unsigned long long)fk << 32) | (unsigned)n;
        if (key < th) {
            int j = TK - 2;
            while (j >= 0 && kept[j] > key) { kept[j + 1] = kept[j]; j--; }
            kept[j + 1] = key;
            th = kept[TK - 1];
        }
    }
    #pragma unroll
    for (int i = 0; i < TK; i++) sk[tid * TK + i] = kept[i];
    __syncthreads();
    for (int r = 0; r < TK; r++) {
        unsigned long long best = ~0ULL;
        #pragma unroll
        for (int i = 0; i < TK; i++) {
            unsigned long long k = sk[tid * TK + i];
            if (k < best) best = k;
        }
        #pragma unroll
        for (int off = 16; off; off >>= 1) {
            unsigned long long o = __shfl_down_sync(0xffffffffu, best, off);
            if (o < best) best = o;
        }
        if ((tid & 31) == 0) swred[tid >> 5] = best;
        __syncthreads();
        if (tid == 0) {
            unsigned long long mn = ~0ULL;
            for (int w = 0; w < TPB / 32; w++) if (swred[w] < mn) mn = swred[w];
            skeep[r] = mn;
        }
        __syncthreads();
        unsigned long long mv = skeep[r];
        #pragma unroll
        for (int i = 0; i < TK; i++)
            if (sk[tid * TK + i] == mv) sk[tid * TK + i] = ~0ULL;
        __syncthreads();
    }
}

__global__ void __launch_bounds__(TPB) kTop(int N, int G) {
    __shared__ unsigned long long sk[TPB * TK];
    __shared__ unsigned long long swred[TPB / 32];
    __shared__ unsigned long long skeep[TK];
    __shared__ int sdk;
    int g = blockIdx.x;
    if (g >= G) return;
    int tid = threadIdx.x;

    // pass 1: masked iou, descending
    topk_pass<true>(&g_iou[(size_t)g * N], N, 0.0f, sk, swred, skeep);
    if (tid == 0) {
        float s = 0.f;
        for (int i = 0; i < TK; i++)
            s += unfkey(~(unsigned)(skeep[i] >> 32));
        int dk = (int)s;
        dk = dk < 1 ? 1 : (dk > TK ? TK : dk);
        sdk = dk;
    }
    __syncthreads();

    // pass 2: masked cost, ascending
    topk_pass<false>(&g_cost[(size_t)g * N], N, BIG_F, sk, swred, skeep);
    int dk = sdk;
    if (tid < dk) {
        int n = (int)(unsigned)skeep[tid];
        atomicAdd(&g_cnt[n], 1);
        atomicMin(&g_mg[n], g);
    }
}

// -------- finalize --------
__global__ void kFinal(float* __restrict__ out, int N, int G) {
    int n = blockIdx.x * blockDim.x + threadIdx.x;
    if (n >= N) return;
    int c = g_cnt[n];
    float gi = 0.f, lb = -1.f, io = -INF_F;
    if (c == 1) {
        int g = g_mg[n];
        gi = (float)g; lb = 1.f;
        io = g_iou[(size_t)g * N + n];
    } else if (c > 1) {
        float best = 3.4e38f; int bg = 0;
        for (int g = 0; g < G; g++) {
            float v = g_cost[(size_t)g * N + n];
            if (v < best) { best = v; bg = g; }
        }
        gi = (float)bg; lb = 1.f;
        io = g_iou[(size_t)bg * N + n];
    }
    out[n] = gi;
    out[N + n] = lb;
    out[2 * N + n] = io;
}

extern "C" void kernel_launch(void* const* d_in, const int* in_sizes, int n_in,
                              void* d_out, int out_size) {
    const float* ps  = (const float*)d_in[0];
    const float* pri = (const float*)d_in[1];
    const float* dec = (const float*)d_in[2];
    const float* gtb = (const float*)d_in[3];
    const int*   gtl = (const int*)d_in[4];
    int N = in_sizes[1] / 4;
    int G = in_sizes[3] / 4;
    int C = in_sizes[0] / N;
    if (N > NMAX || G > GMAX || C > CMAX) return;
    float* out = (float*)d_out;
    (void)out_size; (void)n_in;

    kInit<<<(N + TPB - 1) / TPB, TPB>>>(N);
    kA1<<<(N * C + TPB - 1) / TPB, TPB>>>(ps, N, C);
    kA2<<<(N + TPB - 1) / TPB, TPB>>>(N, C);
    dim3 gb((N + TPB - 1) / TPB, (G + 31) / 32);
    kB<<<gb, TPB>>>(pri, dec, gtb, gtl, N, G);
    kTop<<<G, TPB>>>(N, G);
    kFinal<<<(N + TPB - 1) / TPB, TPB>>>(out, N, G);
}

// round 3
// speedup vs baseline: 1.6389x; 1.6389x over previous
#include <cuda_runtime.h>
#include <stdint.h>

#define NMAX 33600
#define GMAX 128
#define CMAX 80
#define TPB 256
#define TK 10
#define GTILE 16
#define EPSF 1e-7f
#define INF_F 100000.0f
#define BIG_F 100000000.0f
#define CRAD 2.5f
#define NWORDS ((NMAX + 31) / 32)

typedef unsigned long long ull;

// ---- scratch as __device__ globals (allocation-free rule) ----
__device__ float    g_D[(size_t)CMAX * NMAX];     // logit(p) class-major
__device__ float    g_sumL1[NMAX];
__device__ float    g_iou[(size_t)GMAX * NMAX];   // raw IoU, gt-major
__device__ float    g_cost[(size_t)GMAX * NMAX];  // cost incl +INF term, NOT valid-masked
__device__ unsigned g_valid[NWORDS];
__device__ int      g_cnt[NMAX];
__device__ int      g_mg[NMAX];

// monotone float->uint (ascending order preserved)
__device__ __forceinline__ unsigned fkey(float f) {
    unsigned u = __float_as_uint(f);
    return (u & 0x80000000u) ? ~u : (u | 0x80000000u);
}
__device__ __forceinline__ float unfkey(unsigned k) {
    unsigned u = (k & 0x80000000u) ? (k ^ 0x80000000u) : ~k;
    return __uint_as_float(u);
}

// ---------------- kA (C==80 fast path): fused logit + sumL1 ----------------
// Block handles 32 anchors. Coalesced load into padded shared tile, then
// warp w / lane l computes classes {w, w+8, ..., w+72} of anchor n0+l.
// D = logf(p/(1-p)) (1 log/elem); sumL1 via 2 grouped-product logs per 10 elems.
__global__ void __launch_bounds__(TPB) kA80(const float* __restrict__ ps, int N) {
    __shared__ float s[32 * 81];
    __shared__ float part[8][33];
    int tid = threadIdx.x;
    int n0 = blockIdx.x * 32;
    int rows = min(32, N - n0);
    for (int i = tid; i < rows * 80; i += TPB) {
        int r = i / 80, c = i - r * 80;
        s[r * 81 + c] = ps[(size_t)n0 * 80 + i];
    }
    __syncthreads();
    int lane = tid & 31, w = tid >> 5;
    int n = n0 + lane;
    if (lane < rows) {
        float prod0 = 1.f, prod1 = 1.f;
        #pragma unroll
        for (int j = 0; j < 10; j++) {
            int c = w + j * 8;
            float p = s[lane * 81 + c];
            float q = 1.f - p;
            if (j < 5) prod0 *= q; else prod1 *= q;
            g_D[(size_t)c * N + n] = __logf(__fdividef(p, q));
        }
        part[w][lane] = __logf(prod0) + __logf(prod1);
    }
    __syncthreads();
    if (w == 0 && lane < rows) {
        float ssum = 0.f;
        #pragma unroll
        for (int k = 0; k < 8; k++) ssum += part[k][lane];
        g_sumL1[n] = ssum;
    }
}

// generic fallback (never used for this problem's shapes)
__global__ void kAgen(const float* __restrict__ ps, int N, int C) {
    int n = blockIdx.x * blockDim.x + threadIdx.x;
    if (n >= N) return;
    float ssum = 0.f;
    for (int c = 0; c < C; c++) {
        float p = ps[(size_t)n * C + c];
        float L  = fmaxf(__logf(p), -100.f);
        float L1 = fmaxf(__logf(1.f - p), -100.f);
        g_D[(size_t)c * N + n] = L - L1;
        ssum += L1;
    }
    g_sumL1[n] = ssum;
}

// ---------------- init ----------------
__global__ void kInit(int N) {
    int i = blockIdx.x * blockDim.x + threadIdx.x;
    if (i < N) { g_cnt[i] = 0; g_mg[i] = 0x7fffffff; }
    if (i < NWORDS) g_valid[i] = 0u;
}

// -------- kB: pairwise flags + IoU + cost (raw) --------
__global__ void __launch_bounds__(TPB) kB(
    const float* __restrict__ priors, const float* __restrict__ dec,
    const float* __restrict__ gtb, const int* __restrict__ gtl,
    int N, int G)
{
    __shared__ float4 sg0[GTILE];
    __shared__ float4 sg1[GTILE];
    int tid = threadIdx.x;
    int g0 = blockIdx.y * GTILE;
    int gcnt = min(GTILE, G - g0);
    if (tid < gcnt) {
        int g = g0 + tid;
        float x0 = gtb[4*g+0], y0 = gtb[4*g+1], x1 = gtb[4*g+2], y1 = gtb[4*g+3];
        sg0[tid] = make_float4(x0, y0, x1, y1);
        float gcx = (x0 + x1) * 0.5f, gcy = (y0 + y1) * 0.5f;
        float area = fmaxf(x1 - x0, 0.f) * fmaxf(y1 - y0, 0.f);
        sg1[tid] = make_float4(gcx, gcy, area, __int_as_float(gtl[g]));
    }
    __syncthreads();

    int n = blockIdx.x * blockDim.x + tid;
    if (n >= N) return;
    float4 pq = ((const float4*)priors)[n];
    float px = pq.x, py = pq.y;
    float a1 = px + CRAD * pq.z, a2 = px - CRAD * pq.z;
    float b1 = py + CRAD * pq.w, b2 = py - CRAD * pq.w;
    float4 dq = ((const float4*)dec)[n];
    float dx0 = dq.x, dy0 = dq.y, dx1 = dq.z, dy1 = dq.w;
    float aa = fmaxf(dx1 - dx0, 0.f) * fmaxf(dy1 - dy0, 0.f);
    float sL1 = g_sumL1[n];

    bool vacc = false;
    #pragma unroll
    for (int gi = 0; gi < GTILE; gi++) {
        if (gi < gcnt) {
            float4 q0 = sg0[gi];
            float4 q1 = sg1[gi];
            int g = g0 + gi;
            float m1 = fminf(fminf(px - q0.x, py - q0.y), fminf(q0.z - px, q0.w - py));
            float m2 = fminf(fminf(a1 - q1.x, b1 - q1.y), fminf(q1.x - a2, q1.y - b2));
            bool ing = m1 > 0.f, inc = m2 > 0.f;
            vacc = vacc || ing || inc;
            float w = fmaxf(fminf(dx1, q0.z) - fmaxf(dx0, q0.x), 0.f);
            float h = fmaxf(fminf(dy1, q0.w) - fmaxf(dy0, q0.y), 0.f);
            float inter = w * h;
            float uni = fmaxf(aa + q1.z - inter, EPSF);
            float iou = __fdividef(inter, uni);
            int lbl = __float_as_int(q1.w);
            float cls = -g_D[(size_t)lbl * N + n] - sL1;
            float cost = cls - 3.0f * __logf(iou + EPSF);
            if (!(ing && inc)) cost += INF_F;
            g_iou [(size_t)g * N + n] = iou;
            g_cost[(size_t)g * N + n] = cost;
        }
    }
    unsigned m = __ballot_sync(__activemask(), vacc);
    if ((tid & 31) == 0 && m) atomicOr(&g_valid[n >> 5], m);
}

// -------- kTop: per-GT top-10 (registers, branchless bubble) --------
template <bool MAXI>
__device__ void topk_pass(const float* __restrict__ col, int N, float maskval,
                          ull* sk, ull* swred, ull* skeep)
{
    int tid = threadIdx.x;
    ull kept[TK];
    #pragma unroll
    for (int i = 0; i < TK; i++) kept[i] = ~0ULL;
    for (int n = tid; n < N; n += TPB) {
        float v = col[n];
        if (!((g_valid[n >> 5] >> (n & 31)) & 1u)) v = maskval;
        unsigned fk = fkey(v);
        if (MAXI) fk = ~fk;
        ull key = ((ull)fk << 32) | (unsigned)n;
        if (key < kept[TK - 1]) {
            ull x = key;
            #pragma unroll
            for (int i = 0; i < TK; i++) {
                ull lo = (kept[i] < x) ? kept[i] : x;
                ull hi = (kept[i] < x) ? x : kept[i];
                kept[i] = lo; x = hi;
            }
        }
    }
    #pragma unroll
    for (int i = 0; i < TK; i++) sk[tid * TK + i] = kept[i];
    int ptr = 0;
    __syncthreads();
    for (int r = 0; r < TK; r++) {
        ull head = sk[tid * TK + ptr];
        ull best = head;
        #pragma unroll
        for (int off = 16; off; off >>= 1) {
            ull o = __shfl_down_sync(0xffffffffu, best, off);
            if (o < best) best = o;
        }
        if ((tid & 31) == 0) swred[tid >> 5] = best;
        __syncthreads();
        if (tid == 0) {
            ull mn = ~0ULL;
            for (int w = 0; w < TPB / 32; w++) if (swred[w] < mn) mn = swred[w];
            skeep[r] = mn;
        }
        __syncthreads();
        if (head == skeep[r]) ptr++;   // keys unique (index in low bits)
    }
}

__global__ void __launch_bounds__(TPB) kTop(int N, int G) {
    __shared__ ull sk[TPB * TK];
    __shared__ ull swred[TPB / 32];
    __shared__ ull skeep[TK];
    __shared__ int sdk;
    int g = blockIdx.x;
    if (g >= G) return;
    int tid = threadIdx.x;

    // pass 1: masked iou, descending -> dynamic_k
    topk_pass<true>(&g_iou[(size_t)g * N], N, 0.0f, sk, swred, skeep);
    if (tid == 0) {
        float s = 0.f;
        for (int i = 0; i < TK; i++) s += unfkey(~(unsigned)(skeep[i] >> 32));
        int dk = (int)s;
        sdk = dk < 1 ? 1 : (dk > TK ? TK : dk);
    }
    __syncthreads();

    // pass 2: masked cost, ascending -> selected anchors
    topk_pass<false>(&g_cost[(size_t)g * N], N, BIG_F, sk, swred, skeep);
    if (tid < sdk) {
        int n = (int)(unsigned)skeep[tid];
        atomicAdd(&g_cnt[n], 1);
        atomicMin(&g_mg[n], g);
    }
}

// -------- finalize --------
__global__ void kFinal(float* __restrict__ out, int N, int G) {
    int n = blockIdx.x * blockDim.x + threadIdx.x;
    if (n >= N) return;
    int c = g_cnt[n];
    bool val = (g_valid[n >> 5] >> (n & 31)) & 1u;
    float gi = 0.f, lb = -1.f, io = -INF_F;
    if (c == 1) {
        int g = g_mg[n];
        gi = (float)g; lb = 1.f;
        io = val ? g_iou[(size_t)g * N + n] : 0.f;
    } else if (c > 1) {
        lb = 1.f;
        if (!val) { gi = 0.f; io = 0.f; }
        else {
            float best = 3.4e38f; int bg = 0;
            for (int g = 0; g < G; g++) {
                float v = g_cost[(size_t)g * N + n];
                if (v < best) { best = v; bg = g; }
            }
            gi = (float)bg;
            io = g_iou[(size_t)bg * N + n];
        }
    }
    out[n] = gi;
    out[N + n] = lb;
    out[2 * N + n] = io;
}

extern "C" void kernel_launch(void* const* d_in, const int* in_sizes, int n_in,
                              void* d_out, int out_size) {
    const float* ps  = (const float*)d_in[0];
    const float* pri = (const float*)d_in[1];
    const float* dec = (const float*)d_in[2];
    const float* gtb = (const float*)d_in[3];
    const int*   gtl = (const int*)d_in[4];
    int N = in_sizes[1] / 4;
    int G = in_sizes[3] / 4;
    int C = in_sizes[0] / N;
    if (N > NMAX || G > GMAX || C > CMAX) return;
    float* out = (float*)d_out;
    (void)out_size; (void)n_in;

    kInit<<<(N + TPB - 1) / TPB, TPB>>>(N);
    if (C == 80)
        kA80<<<(N + 31) / 32, TPB>>>(ps, N);
    else
        kAgen<<<(N + TPB - 1) / TPB, TPB>>>(ps, N, C);
    dim3 gb((N + TPB - 1) / TPB, (G + GTILE - 1) / GTILE);
    kB<<<gb, TPB>>>(pri, dec, gtb, gtl, N, G);
    kTop<<<G, TPB>>>(N, G);
    kFinal<<<(N + TPB - 1) / TPB, TPB>>>(out, N, G);
}

// round 4
// speedup vs baseline: 2.3013x; 1.4042x over previous
#include <cuda_runtime.h>
#include <stdint.h>

#define NMAX 33600
#define GMAX 128
#define CMAX 80
#define TPB 256
#define TPBM 128
#define TK 10
#define GTILE 16
#define SPLIT 8
#define EPSF 1e-7f
#define INF_F 100000.0f
#define BIG_F 100000000.0f
#define CRAD 2.5f
#define NWORDS ((NMAX + 31) / 32)

typedef unsigned long long ull;

// ---- scratch as __device__ globals (allocation-free rule) ----
__device__ float    g_D[(size_t)CMAX * NMAX];     // logit(p) class-major (only used classes)
__device__ float    g_sumL1[NMAX];
__device__ float    g_iou[(size_t)GMAX * NMAX];   // raw IoU, gt-major
__device__ float    g_cost[(size_t)GMAX * NMAX];  // cost incl +INF term, NOT valid-masked
__device__ unsigned g_valid[NWORDS];
__device__ int      g_cnt[NMAX];
__device__ int      g_mg[NMAX];
__device__ int      g_flags[CMAX];
__device__ ull      g_piou [GMAX * SPLIT * TK];
__device__ ull      g_pcost[GMAX * SPLIT * TK];

// monotone float->uint (ascending order preserved)
__device__ __forceinline__ unsigned fkey(float f) {
    unsigned u = __float_as_uint(f);
    return (u & 0x80000000u) ? ~u : (u | 0x80000000u);
}
__device__ __forceinline__ float unfkey(unsigned k) {
    unsigned u = (k & 0x80000000u) ? (k ^ 0x80000000u) : ~k;
    return __uint_as_float(u);
}

// ---------------- flags: which classes appear in gt_labels ----------------
__global__ void kFlags(const int* __restrict__ gtl, int G) {
    int t = threadIdx.x;
    if (t < CMAX) g_flags[t] = 0;
    __syncthreads();
    for (int i = t; i < G; i += blockDim.x) g_flags[gtl[i]] = 1;
}

// ---------------- kA (C==80 fast path): fused logit + sumL1 ----------------
__global__ void __launch_bounds__(TPB) kA80(const float* __restrict__ ps, int N) {
    __shared__ float s[32 * 81];
    __shared__ float part[8][33];
    int tid = threadIdx.x;
    int n0 = blockIdx.x * 32;
    int rows = min(32, N - n0);
    for (int i = tid; i < rows * 80; i += TPB) {
        int r = i / 80, c = i - r * 80;
        s[r * 81 + c] = ps[(size_t)n0 * 80 + i];
    }
    __syncthreads();
    int lane = tid & 31, w = tid >> 5;
    int n = n0 + lane;
    if (lane < rows) {
        float prod0 = 1.f, prod1 = 1.f;
        #pragma unroll
        for (int j = 0; j < 10; j++) {
            int c = w + j * 8;
            float p = s[lane * 81 + c];
            float q = 1.f - p;
            if (j < 5) prod0 *= q; else prod1 *= q;
            if (g_flags[c])
                g_D[(size_t)c * N + n] = __logf(__fdividef(p, q));
        }
        part[w][lane] = __logf(prod0) + __logf(prod1);
    }
    __syncthreads();
    if (w == 0 && lane < rows) {
        float ssum = 0.f;
        #pragma unroll
        for (int k = 0; k < 8; k++) ssum += part[k][lane];
        g_sumL1[n] = ssum;
    }
}

// generic fallback
__global__ void kAgen(const float* __restrict__ ps, int N, int C) {
    int n = blockIdx.x * blockDim.x + threadIdx.x;
    if (n >= N) return;
    float ssum = 0.f;
    for (int c = 0; c < C; c++) {
        float p = ps[(size_t)n * C + c];
        float L  = fmaxf(__logf(p), -100.f);
        float L1 = fmaxf(__logf(1.f - p), -100.f);
        g_D[(size_t)c * N + n] = L - L1;
        ssum += L1;
    }
    g_sumL1[n] = ssum;
}

// ---------------- init ----------------
__global__ void kInit(int N) {
    int i = blockIdx.x * blockDim.x + threadIdx.x;
    if (i < N) { g_cnt[i] = 0; g_mg[i] = 0x7fffffff; }
    if (i < NWORDS) g_valid[i] = 0u;
}

// -------- kB: pairwise flags + IoU + cost (raw) --------
__global__ void __launch_bounds__(TPB) kB(
    const float* __restrict__ priors, const float* __restrict__ dec,
    const float* __restrict__ gtb, const int* __restrict__ gtl,
    int N, int G)
{
    __shared__ float4 sg0[GTILE];
    __shared__ float4 sg1[GTILE];
    int tid = threadIdx.x;
    int g0 = blockIdx.y * GTILE;
    int gcnt = min(GTILE, G - g0);
    if (tid < gcnt) {
        int g = g0 + tid;
        float x0 = gtb[4*g+0], y0 = gtb[4*g+1], x1 = gtb[4*g+2], y1 = gtb[4*g+3];
        sg0[tid] = make_float4(x0, y0, x1, y1);
        float gcx = (x0 + x1) * 0.5f, gcy = (y0 + y1) * 0.5f;
        float area = fmaxf(x1 - x0, 0.f) * fmaxf(y1 - y0, 0.f);
        sg1[tid] = make_float4(gcx, gcy, area, __int_as_float(gtl[g]));
    }
    __syncthreads();

    int n = blockIdx.x * blockDim.x + tid;
    if (n >= N) return;
    float4 pq = ((const float4*)priors)[n];
    float px = pq.x, py = pq.y;
    float a1 = px + CRAD * pq.z, a2 = px - CRAD * pq.z;
    float b1 = py + CRAD * pq.w, b2 = py - CRAD * pq.w;
    float4 dq = ((const float4*)dec)[n];
    float dx0 = dq.x, dy0 = dq.y, dx1 = dq.z, dy1 = dq.w;
    float aa = fmaxf(dx1 - dx0, 0.f) * fmaxf(dy1 - dy0, 0.f);
    float sL1 = g_sumL1[n];

    bool vacc = false;
    #pragma unroll
    for (int gi = 0; gi < GTILE; gi++) {
        if (gi < gcnt) {
            float4 q0 = sg0[gi];
            float4 q1 = sg1[gi];
            int g = g0 + gi;
            float m1 = fminf(fminf(px - q0.x, py - q0.y), fminf(q0.z - px, q0.w - py));
            float m2 = fminf(fminf(a1 - q1.x, b1 - q1.y), fminf(q1.x - a2, q1.y - b2));
            bool ing = m1 > 0.f, inc = m2 > 0.f;
            vacc = vacc || ing || inc;
            float w = fmaxf(fminf(dx1, q0.z) - fmaxf(dx0, q0.x), 0.f);
            float h = fmaxf(fminf(dy1, q0.w) - fmaxf(dy0, q0.y), 0.f);
            float inter = w * h;
            float uni = fmaxf(aa + q1.z - inter, EPSF);
            float iou = __fdividef(inter, uni);
            int lbl = __float_as_int(q1.w);
            float cls = -g_D[(size_t)lbl * N + n] - sL1;
            float cost = cls - 3.0f * __logf(iou + EPSF);
            if (!(ing && inc)) cost += INF_F;
            g_iou [(size_t)g * N + n] = iou;
            g_cost[(size_t)g * N + n] = cost;
        }
    }
    unsigned m = __ballot_sync(__activemask(), vacc);
    if ((tid & 31) == 0 && m) atomicOr(&g_valid[n >> 5], m);
}

// -------- top-10 of one column slice (block-wide), results in skeep --------
template <bool MAXI>
__device__ void topk_slice(const float* __restrict__ col, int n0, int n1,
                           float maskval, ull* sk, ull* swred, ull* skeep)
{
    int tid = threadIdx.x;
    ull kept[TK];
    #pragma unroll
    for (int i = 0; i < TK; i++) kept[i] = ~0ULL;

    int n1v = n1 & ~3;
    for (int n = n0 + tid * 4; n < n1v; n += TPB * 4) {
        float4 v4 = *reinterpret_cast<const float4*>(col + n);
        unsigned wv = g_valid[n >> 5] >> (n & 31);
        float vv[4] = {v4.x, v4.y, v4.z, v4.w};
        #pragma unroll
        for (int k = 0; k < 4; k++) {
            float v = ((wv >> k) & 1u) ? vv[k] : maskval;
            unsigned fk = fkey(v);
            if (MAXI) fk = ~fk;
            ull key = ((ull)fk << 32) | (unsigned)(n + k);
            if (key < kept[TK - 1]) {
                ull x = key;
                #pragma unroll
                for (int i = 0; i < TK; i++) {
                    ull lo = (kept[i] < x) ? kept[i] : x;
                    ull hi = (kept[i] < x) ? x : kept[i];
                    kept[i] = lo; x = hi;
                }
            }
        }
    }
    for (int n = n1v + tid; n < n1; n += TPB) {
        float v = col[n];
        if (!((g_valid[n >> 5] >> (n & 31)) & 1u)) v = maskval;
        unsigned fk = fkey(v);
        if (MAXI) fk = ~fk;
        ull key = ((ull)fk << 32) | (unsigned)n;
        if (key < kept[TK - 1]) {
            ull x = key;
            #pragma unroll
            for (int i = 0; i < TK; i++) {
                ull lo = (kept[i] < x) ? kept[i] : x;
                ull hi = (kept[i] < x) ? x : kept[i];
                kept[i] = lo; x = hi;
            }
        }
    }

    #pragma unroll
    for (int i = 0; i < TK; i++) sk[tid * TK + i] = kept[i];
    int ptr = 0;
    __syncthreads();
    for (int r = 0; r < TK; r++) {
        ull head = sk[tid * TK + ptr];
        ull best = head;
        #pragma unroll
        for (int off = 16; off; off >>= 1) {
            ull o = __shfl_down_sync(0xffffffffu, best, off);
            if (o < best) best = o;
        }
        if ((tid & 31) == 0) swred[tid >> 5] = best;
        __syncthreads();
        if (tid == 0) {
            ull mn = ~0ULL;
            for (int w = 0; w < TPB / 32; w++) if (swred[w] < mn) mn = swred[w];
            skeep[r] = mn;
        }
        __syncthreads();
        if (head == skeep[r] && ptr < TK - 1) ptr++;
    }
}

// -------- kTopPart: grid (G, SPLIT) — partial top-10 per slice --------
__global__ void __launch_bounds__(TPB) kTopPart(int N) {
    __shared__ ull sk[TPB * TK];
    __shared__ ull swred[TPB / 32];
    __shared__ ull skeep[TK];
    int g = blockIdx.x, s = blockIdx.y;
    int tid = threadIdx.x;
    int len = (((N + SPLIT - 1) / SPLIT) + 3) & ~3;
    int n0 = s * len;
    int n1 = min(N, n0 + len);
    if (n0 >= n1) {
        if (tid < TK) {
            g_piou [(g * SPLIT + s) * TK + tid] = ~0ULL;
            g_pcost[(g * SPLIT + s) * TK + tid] = ~0ULL;
        }
        return;
    }
    topk_slice<true>(&g_iou[(size_t)g * N], n0, n1, 0.0f, sk, swred, skeep);
    if (tid < TK) g_piou[(g * SPLIT + s) * TK + tid] = skeep[tid];
    __syncthreads();
    topk_slice<false>(&g_cost[(size_t)g * N], n0, n1, BIG_F, sk, swred, skeep);
    if (tid < TK) g_pcost[(g * SPLIT + s) * TK + tid] = skeep[tid];
}

// -------- kTopMerge: grid G — merge partials, dynamic_k, atomics --------
__global__ void __launch_bounds__(TPBM) kTopMerge(int G) {
    __shared__ ull swred[TPBM / 32];
    __shared__ ull skeep[TK];
    __shared__ int sdk;
    int g = blockIdx.x;
    int tid = threadIdx.x;

    // iou merge (keys already "smaller = better-iou")
    ull key = (tid < SPLIT * TK) ? g_piou[g * SPLIT * TK + tid] : ~0ULL;
    for (int r = 0; r < TK; r++) {
        ull best = key;
        #pragma unroll
        for (int off = 16; off; off >>= 1) {
            ull o = __shfl_down_sync(0xffffffffu, best, off);
            if (o < best) best = o;
        }
        if ((tid & 31) == 0) swred[tid >> 5] = best;
        __syncthreads();
        if (tid == 0) {
            ull mn = ~0ULL;
            for (int w = 0; w < TPBM / 32; w++) if (swred[w] < mn) mn = swred[w];
            skeep[r] = mn;
        }
        __syncthreads();
        if (key == skeep[r]) key = ~0ULL;
    }
    if (tid == 0) {
        float ssum = 0.f;
        for (int i = 0; i < TK; i++)
            if (skeep[i] != ~0ULL)
                ssum += unfkey(~(unsigned)(skeep[i] >> 32));
        int dk = (int)ssum;
        sdk = dk < 1 ? 1 : (dk > TK ? TK : dk);
    }
    __syncthreads();

    // cost merge
    key = (tid < SPLIT * TK) ? g_pcost[g * SPLIT * TK + tid] : ~0ULL;
    for (int r = 0; r < TK; r++) {
        ull best = key;
        #pragma unroll
        for (int off = 16; off; off >>= 1) {
            ull o = __shfl_down_sync(0xffffffffu, best, off);
            if (o < best) best = o;
        }
        if ((tid & 31) == 0) swred[tid >> 5] = best;
        __syncthreads();
        if (tid == 0) {
            ull mn = ~0ULL;
            for (int w = 0; w < TPBM / 32; w++) if (swred[w] < mn) mn = swred[w];
            skeep[r] = mn;
        }
        __syncthreads();
        if (key == skeep[r]) key = ~0ULL;
    }
    if (tid < sdk && skeep[tid] != ~0ULL) {
        int n = (int)(unsigned)skeep[tid];
        atomicAdd(&g_cnt[n], 1);
        atomicMin(&g_mg[n], g);
    }
}

// -------- finalize --------
__global__ void kFinal(float* __restrict__ out, int N, int G) {
    int n = blockIdx.x * blockDim.x + threadIdx.x;
    if (n >= N) return;
    int c = g_cnt[n];
    bool val = (g_valid[n >> 5] >> (n & 31)) & 1u;
    float gi = 0.f, lb = -1.f, io = -INF_F;
    if (c == 1) {
        int g = g_mg[n];
        gi = (float)g; lb = 1.f;
        io = val ? g_iou[(size_t)g * N + n] : 0.f;
    } else if (c > 1) {
        lb = 1.f;
        if (!val) { gi = 0.f; io = 0.f; }
        else {
            float best = 3.4e38f; int bg = 0;
            for (int g = 0; g < G; g++) {
                float v = g_cost[(size_t)g * N + n];
                if (v < best) { best = v; bg = g; }
            }
            gi = (float)bg;
            io = g_iou[(size_t)bg * N + n];
        }
    }
    out[n] = gi;
    out[N + n] = lb;
    out[2 * N + n] = io;
}

extern "C" void kernel_launch(void* const* d_in, const int* in_sizes, int n_in,
                              void* d_out, int out_size) {
    const float* ps  = (const float*)d_in[0];
    const float* pri = (const float*)d_in[1];
    const float* dec = (const float*)d_in[2];
    const float* gtb = (const float*)d_in[3];
    const int*   gtl = (const int*)d_in[4];
    int N = in_sizes[1] / 4;
    int G = in_sizes[3] / 4;
    int C = in_sizes[0] / N;
    if (N > NMAX || G > GMAX || C > CMAX) return;
    float* out = (float*)d_out;
    (void)out_size; (void)n_in;

    kInit<<<(N + TPB - 1) / TPB, TPB>>>(N);
    kFlags<<<1, 128>>>(gtl, G);
    if (C == 80)
        kA80<<<(N + 31) / 32, TPB>>>(ps, N);
    else
        kAgen<<<(N + TPB - 1) / TPB, TPB>>>(ps, N, C);
    dim3 gb((N + TPB - 1) / TPB, (G + GTILE - 1) / GTILE);
    kB<<<gb, TPB>>>(pri, dec, gtb, gtl, N, G);
    dim3 gt(G, SPLIT);
    kTopPart<<<gt, TPB>>>(N);
    kTopMerge<<<G, TPBM>>>(G);
    kFinal<<<(N + TPB - 1) / TPB, TPB>>>(out, N, G);
}

// round 5
// speedup vs baseline: 2.4154x; 1.0496x over previous
#include <cuda_runtime.h>
#include <stdint.h>

#define NMAX 33600
#define GMAX 128
#define CMAX 80
#define TPB 256
#define TK 10
#define GTILE 16
#define SPLIT 8
#define NW (TPB / 32)
#define TOTK (SPLIT * NW * TK)          // 640 partial keys per gt per list
#define KM ((TOTK + TPB - 1) / TPB)     // keys per thread in merge (3)
#define EPSF 1e-7f
#define INF_F 100000.0f
#define BIG_F 100000000.0f
#define CRAD 2.5f
#define NWORDS ((NMAX + 31) / 32)

typedef unsigned long long ull;

// ---- scratch as __device__ globals (allocation-free rule) ----
__device__ float    g_D[(size_t)CMAX * NMAX];    // logit(p), class-major (used classes)
__device__ float    g_sumL1[NMAX];
__device__ float2   g_ic[(size_t)GMAX * NMAX];   // {iou, cost} gt-major
__device__ unsigned g_valid[NWORDS];
__device__ int      g_cnt[NMAX];
__device__ int      g_mg[NMAX];
__device__ int      g_flags[CMAX];
__device__ int      g_done[GMAX];
__device__ ull      g_piou [GMAX * TOTK];
__device__ ull      g_pcost[GMAX * TOTK];

// monotone float->uint (ascending order preserved)
__device__ __forceinline__ unsigned fkey(float f) {
    unsigned u = __float_as_uint(f);
    return (u & 0x80000000u) ? ~u : (u | 0x80000000u);
}
__device__ __forceinline__ float unfkey(unsigned k) {
    unsigned u = (k & 0x80000000u) ? (k ^ 0x80000000u) : ~k;
    return __uint_as_float(u);
}

// branchless sorted-insert into ascending 10-list (constant indices only)
__device__ __forceinline__ void ins10(ull* a, ull x) {
    #pragma unroll
    for (int i = 0; i < TK; i++) {
        ull lo = a[i] < x ? a[i] : x;
        ull hi = a[i] < x ? x : a[i];
        a[i] = lo; x = hi;
    }
}

// -------- kSetup: init counters/valid + label flags + done counters --------
__global__ void kSetup(const int* __restrict__ gtl, int N, int G) {
    int tid = threadIdx.x;
    int i = blockIdx.x * blockDim.x + tid;
    if (i < N) { g_cnt[i] = 0; g_mg[i] = 0x7fffffff; }
    if (i < NWORDS) g_valid[i] = 0u;
    if (blockIdx.x == 0) {
        if (tid < CMAX) g_flags[tid] = 0;
        if (tid < GMAX) g_done[tid] = 0;
        __syncthreads();
        for (int j = tid; j < G; j += TPB) g_flags[gtl[j]] = 1;
    }
}

// -------- kA80: fused logit + sumL1 (C==80 fast path) --------
__global__ void __launch_bounds__(TPB) kA80(const float* __restrict__ ps, int N) {
    __shared__ float s[32 * 81];
    __shared__ float part[8][33];
    int tid = threadIdx.x;
    int n0 = blockIdx.x * 32;
    int rows = min(32, N - n0);
    for (int i = tid; i < rows * 80; i += TPB) {
        int r = i / 80, c = i - r * 80;
        s[r * 81 + c] = ps[(size_t)n0 * 80 + i];
    }
    __syncthreads();
    int lane = tid & 31, w = tid >> 5;
    int n = n0 + lane;
    if (lane < rows) {
        float prod0 = 1.f, prod1 = 1.f;
        #pragma unroll
        for (int j = 0; j < 10; j++) {
            int c = w + j * 8;
            float p = s[lane * 81 + c];
            float q = 1.f - p;
            if (j < 5) prod0 *= q; else prod1 *= q;
            if (g_flags[c])
                g_D[(size_t)c * N + n] = __logf(__fdividef(p, q));
        }
        part[w][lane] = __logf(prod0) + __logf(prod1);
    }
    __syncthreads();
    if (w == 0 && lane < rows) {
        float ssum = 0.f;
        #pragma unroll
        for (int k = 0; k < 8; k++) ssum += part[k][lane];
        g_sumL1[n] = ssum;
    }
}

// generic fallback
__global__ void kAgen(const float* __restrict__ ps, int N, int C) {
    int n = blockIdx.x * blockDim.x + threadIdx.x;
    if (n >= N) return;
    float ssum = 0.f;
    for (int c = 0; c < C; c++) {
        float p = ps[(size_t)n * C + c];
        float L  = fmaxf(__logf(p), -100.f);
        float L1 = fmaxf(__logf(1.f - p), -100.f);
        g_D[(size_t)c * N + n] = L - L1;
        ssum += L1;
    }
    g_sumL1[n] = ssum;
}

// -------- kB: pairwise IoU + cost, single float2 store per pair --------
__global__ void __launch_bounds__(TPB) kB(
    const float* __restrict__ priors, const float* __restrict__ dec,
    const float* __restrict__ gtb, const int* __restrict__ gtl,
    int N, int G)
{
    __shared__ float4 sg0[GTILE];
    __shared__ float4 sg1[GTILE];
    int tid = threadIdx.x;
    int g0 = blockIdx.y * GTILE;
    int gcnt = min(GTILE, G - g0);
    if (tid < gcnt) {
        int g = g0 + tid;
        float x0 = gtb[4*g+0], y0 = gtb[4*g+1], x1 = gtb[4*g+2], y1 = gtb[4*g+3];
        sg0[tid] = make_float4(x0, y0, x1, y1);
        float gcx = (x0 + x1) * 0.5f, gcy = (y0 + y1) * 0.5f;
        float area = fmaxf(x1 - x0, 0.f) * fmaxf(y1 - y0, 0.f);
        sg1[tid] = make_float4(gcx, gcy, area, __int_as_float(gtl[g]));
    }
    __syncthreads();

    int n = blockIdx.x * blockDim.x + tid;
    if (n >= N) return;
    float4 pq = ((const float4*)priors)[n];
    float px = pq.x, py = pq.y;
    float a1 = px + CRAD * pq.z, a2 = px - CRAD * pq.z;
    float b1 = py + CRAD * pq.w, b2 = py - CRAD * pq.w;
    float4 dq = ((const float4*)dec)[n];
    float dx0 = dq.x, dy0 = dq.y, dx1 = dq.z, dy1 = dq.w;
    float aa = fmaxf(dx1 - dx0, 0.f) * fmaxf(dy1 - dy0, 0.f);
    float sL1 = g_sumL1[n];

    bool vacc = false;
    #pragma unroll
    for (int gi = 0; gi < GTILE; gi++) {
        if (gi < gcnt) {
            float4 q0 = sg0[gi];
            float4 q1 = sg1[gi];
            int g = g0 + gi;
            float m1 = fminf(fminf(px - q0.x, py - q0.y), fminf(q0.z - px, q0.w - py));
            float m2 = fminf(fminf(a1 - q1.x, b1 - q1.y), fminf(q1.x - a2, q1.y - b2));
            bool ing = m1 > 0.f, inc = m2 > 0.f;
            vacc = vacc || ing || inc;
            float w = fmaxf(fminf(dx1, q0.z) - fmaxf(dx0, q0.x), 0.f);
            float h = fmaxf(fminf(dy1, q0.w) - fmaxf(dy0, q0.y), 0.f);
            float inter = w * h;
            float uni = fmaxf(aa + q1.z - inter, EPSF);
            float iou = __fdividef(inter, uni);
            int lbl = __float_as_int(q1.w);
            float cls = -g_D[(size_t)lbl * N + n] - sL1;
            float cost = cls - 3.0f * __logf(iou + EPSF);
            if (!(ing && inc)) cost += INF_F;
            g_ic[(size_t)g * N + n] = make_float2(iou, cost);
        }
    }
    unsigned m = __ballot_sync(__activemask(), vacc);
    if ((tid & 31) == 0 && m) atomicOr(&g_valid[n >> 5], m);
}

// warp-level extraction: lanes 0..9 end with r-th smallest in `mine`
__device__ __forceinline__ void wextract(ull kept[TK], int lane, ull& mine) {
    #pragma unroll
    for (int r = 0; r < TK; r++) {
        ull mn = kept[0];
        #pragma unroll
        for (int off = 16; off; off >>= 1) {
            ull o = __shfl_xor_sync(0xffffffffu, mn, off);
            if (o < mn) mn = o;
        }
        if (kept[0] == mn) {          // keys unique -> exactly one lane
            #pragma unroll
            for (int i = 0; i < TK - 1; i++) kept[i] = kept[i + 1];
            kept[TK - 1] = ~0ULL;
        }
        if (lane == r) mine = mn;
    }
}

// -------- kTopPart: grid (G, SPLIT); fused scan of both lists, warp-level
//          partials, and last-block-per-g merge + dynamic_k + atomics --------
__global__ void __launch_bounds__(TPB) kTopPart(int N) {
    __shared__ ull swred[NW];
    __shared__ int sfl;
    int g = blockIdx.x, s = blockIdx.y;
    int tid = threadIdx.x, lane = tid & 31, w = tid >> 5;
    int len = (((N + SPLIT - 1) / SPLIT) + 3) & ~3;
    int n0 = s * len;
    int n1 = min(N, n0 + len);

    ull ki[TK], kc[TK];
    #pragma unroll
    for (int i = 0; i < TK; i++) { ki[i] = ~0ULL; kc[i] = ~0ULL; }

    const float2* col = g_ic + (size_t)g * N;
    if (n0 < n1) {
        int n1v = n0 + ((n1 - n0) & ~1);
        for (int n = n0 + tid * 2; n < n1v; n += TPB * 2) {
            float4 v = *reinterpret_cast<const float4*>(col + n);
            unsigned wv = g_valid[n >> 5] >> (n & 31);
            {
                bool vd = wv & 1u;
                float io = vd ? v.x : 0.f;
                float co = vd ? v.y : BIG_F;
                ull keyi = ((ull)(unsigned)~fkey(io) << 32) | (unsigned)n;
                if (keyi < ki[TK - 1]) ins10(ki, keyi);
                ull keyc = ((ull)fkey(co) << 32) | (unsigned)n;
                if (keyc < kc[TK - 1]) ins10(kc, keyc);
            }
            {
                int n2 = n + 1;
                bool vd = (wv >> 1) & 1u;
                float io = vd ? v.z : 0.f;
                float co = vd ? v.w : BIG_F;
                ull keyi = ((ull)(unsigned)~fkey(io) << 32) | (unsigned)n2;
                if (keyi < ki[TK - 1]) ins10(ki, keyi);
                ull keyc = ((ull)fkey(co) << 32) | (unsigned)n2;
                if (keyc < kc[TK - 1]) ins10(kc, keyc);
            }
        }
        if (tid == 0 && n1v < n1) {
            int n = n1v;
            float2 p = col[n];
            bool vd = (g_valid[n >> 5] >> (n & 31)) & 1u;
            float io = vd ? p.x : 0.f;
            float co = vd ? p.y : BIG_F;
            ins10(ki, ((ull)(unsigned)~fkey(io) << 32) | (unsigned)n);
            ins10(kc, ((ull)fkey(co) << 32) | (unsigned)n);
        }
    }

    ull mi = ~0ULL, mc = ~0ULL;
    wextract(ki, lane, mi);
    wextract(kc, lane, mc);
    int base = g * TOTK + (s * NW + w) * TK;
    if (lane < TK) {
        g_piou [base + lane] = mi;
        g_pcost[base + lane] = mc;
    }
    __syncthreads();
    if (tid == 0) {
        __threadfence();
        int old = atomicAdd(&g_done[g], 1);
        sfl = (old == SPLIT - 1);
    }
    __syncthreads();
    if (!sfl) return;

    // ---------------- merge (elected last block for this g) ----------------
    // iou list -> dynamic_k
    ull kp[KM];
    #pragma unroll
    for (int i = 0; i < KM; i++) {
        int j = tid + i * TPB;
        kp[i] = (j < TOTK) ? __ldcg(&g_piou[g * TOTK + j]) : ~0ULL;
    }
    // sort KM=3 ascending
    {
        ull a = kp[0], b = kp[1], c = kp[2];
        ull t;
        if (b < a) { t = a; a = b; b = t; }
        if (c < b) { t = b; b = c; c = t; }
        if (b < a) { t = a; a = b; b = t; }
        kp[0] = a; kp[1] = b; kp[2] = c;
    }
    float ssum = 0.f;
    for (int r = 0; r < TK; r++) {
        ull mn = kp[0];
        #pragma unroll
        for (int off = 16; off; off >>= 1) {
            ull o = __shfl_xor_sync(0xffffffffu, mn, off);
            if (o < mn) mn = o;
        }
        if (lane == 0) swred[w] = mn;
        __syncthreads();
        ull bm = swred[0];
        #pragma unroll
        for (int k = 1; k < NW; k++) if (swred[k] < bm) bm = swred[k];
        __syncthreads();
        if (kp[0] == bm) {
            #pragma unroll
            for (int i = 0; i < KM - 1; i++) kp[i] = kp[i + 1];
            kp[KM - 1] = ~0ULL;
        }
        if (bm != ~0ULL) ssum += unfkey(~(unsigned)(bm >> 32));
    }
    int dk = (int)ssum;
    dk = dk < 1 ? 1 : (dk > TK ? TK : dk);

    // cost list -> selections
    #pragma unroll
    for (int i = 0; i < KM; i++) {
        int j = tid + i * TPB;
        kp[i] = (j < TOTK) ? __ldcg(&g_pcost[g * TOTK + j]) : ~0ULL;
    }
    {
        ull a = kp[0], b = kp[1], c = kp[2];
        ull t;
        if (b < a) { t = a; a = b; b = t; }
        if (c < b) { t = b; b = c; c = t; }
        if (b < a) { t = a; a = b; b = t; }
        kp[0] = a; kp[1] = b; kp[2] = c;
    }
    ull myv = ~0ULL;
    for (int r = 0; r < TK; r++) {
        ull mn = kp[0];
        #pragma unroll
        for (int off = 16; off; off >>= 1) {
            ull o = __shfl_xor_sync(0xffffffffu, mn, off);
            if (o < mn) mn = o;
        }
        if (lane == 0) swred[w] = mn;
        __syncthreads();
        ull bm = swred[0];
        #pragma unroll
        for (int k = 1; k < NW; k++) if (swred[k] < bm) bm = swred[k];
        __syncthreads();
        if (kp[0] == bm) {
            #pragma unroll
            for (int i = 0; i < KM - 1; i++) kp[i] = kp[i + 1];
            kp[KM - 1] = ~0ULL;
        }
        if (tid == r) myv = bm;
    }
    if (tid < dk && myv != ~0ULL) {
        int n = (int)(unsigned)myv;
        atomicAdd(&g_cnt[n], 1);
        atomicMin(&g_mg[n], g);
    }
}

// -------- finalize --------
__global__ void kFinal(float* __restrict__ out, int N, int G) {
    int n = blockIdx.x * blockDim.x + threadIdx.x;
    if (n >= N) return;
    int c = g_cnt[n];
    bool val = (g_valid[n >> 5] >> (n & 31)) & 1u;
    float gi = 0.f, lb = -1.f, io = -INF_F;
    if (c == 1) {
        int g = g_mg[n];
        gi = (float)g; lb = 1.f;
        io = val ? g_ic[(size_t)g * N + n].x : 0.f;
    } else if (c > 1) {
        lb = 1.f;
        if (!val) { gi = 0.f; io = 0.f; }
        else {
            float best = 3.4e38f; int bg = 0;
            for (int g = 0; g < G; g++) {
                float v = g_ic[(size_t)g * N + n].y;
                if (v < best) { best = v; bg = g; }
            }
            gi = (float)bg;
            io = g_ic[(size_t)bg * N + n].x;
        }
    }
    out[n] = gi;
    out[N + n] = lb;
    out[2 * N + n] = io;
}

extern "C" void kernel_launch(void* const* d_in, const int* in_sizes, int n_in,
                              void* d_out, int out_size) {
    const float* ps  = (const float*)d_in[0];
    const float* pri = (const float*)d_in[1];
    const float* dec = (const float*)d_in[2];
    const float* gtb = (const float*)d_in[3];
    const int*   gtl = (const int*)d_in[4];
    int N = in_sizes[1] / 4;
    int G = in_sizes[3] / 4;
    int C = in_sizes[0] / N;
    if (N > NMAX || G > GMAX || C > CMAX) return;
    float* out = (float*)d_out;
    (void)out_size; (void)n_in;

    kSetup<<<(N + TPB - 1) / TPB, TPB>>>(gtl, N, G);
    if (C == 80)
        kA80<<<(N + 31) / 32, TPB>>>(ps, N);
    else
        kAgen<<<(N + TPB - 1) / TPB, TPB>>>(ps, N, C);
    dim3 gb((N + TPB - 1) / TPB, (G + GTILE - 1) / GTILE);
    kB<<<gb, TPB>>>(pri, dec, gtb, gtl, N, G);
    dim3 gt(G, SPLIT);
    kTopPart<<<gt, TPB>>>(N);
    kFinal<<<(N + TPB - 1) / TPB, TPB>>>(out, N, G);
}

// round 6
// speedup vs baseline: 3.0235x; 1.2518x over previous
#include <cuda_runtime.h>
#include <stdint.h>

#define NMAX 33600
#define GMAX 128
#define CMAX 80
#define TPB 256
#define TK 10
#define GTILE 16
#define SPLIT 8
#define NW (TPB / 32)
#define CAP 768
#define TOTK (SPLIT * TK)               // 80 partial keys per gt per list
#define EPSF 1e-7f
#define INF_F 100000.0f
#define BIG_F 100000000.0f
#define CRAD 2.5f
#define NWORDS ((NMAX + 31) / 32)
#define FULLM 0xffffffffu

typedef unsigned long long ull;

// ---- scratch as __device__ globals (allocation-free rule) ----
__device__ float    g_D[(size_t)CMAX * NMAX];    // logit(p), class-major (used classes)
__device__ float    g_sumL1[NMAX];
__device__ float2   g_ic[(size_t)GMAX * NMAX];   // {iou, cost} gt-major
__device__ unsigned g_valid[NWORDS];
__device__ int      g_cnt[NMAX];
__device__ int      g_mg[NMAX];
__device__ int      g_flags[CMAX];
__device__ int      g_done[GMAX];
__device__ ull      g_piou [GMAX * TOTK];
__device__ ull      g_pcost[GMAX * TOTK];

// monotone float->uint (ascending order preserved)
__device__ __forceinline__ unsigned fkey(float f) {
    unsigned u = __float_as_uint(f);
    return (u & 0x80000000u) ? ~u : (u | 0x80000000u);
}
__device__ __forceinline__ float unfkey(unsigned k) {
    unsigned u = (k & 0x80000000u) ? (k ^ 0x80000000u) : ~k;
    return __uint_as_float(u);
}

__device__ __forceinline__ ull umin64(ull a, ull b) { return a < b ? a : b; }

// warp-collective top-2 update; m1<=m2 kept uniform across warp
__device__ __forceinline__ void wtop2(ull& m1, ull& m2, ull k) {
    unsigned mk = __ballot_sync(FULLM, k < m2);
    while (mk) {
        int l = __ffs(mk) - 1;
        mk &= mk - 1;
        ull kk = __shfl_sync(FULLM, k, l);
        if (kk < m1) { m2 = m1; m1 = kk; }
        else if (kk < m2) m2 = kk;
    }
}

// -------- kSetup: init counters/valid + label flags + done counters --------
__global__ void kSetup(const int* __restrict__ gtl, int N, int G) {
    int tid = threadIdx.x;
    int i = blockIdx.x * blockDim.x + tid;
    if (i < N) { g_cnt[i] = 0; g_mg[i] = 0x7fffffff; }
    if (i < NWORDS) g_valid[i] = 0u;
    if (blockIdx.x == 0) {
        if (tid < CMAX) g_flags[tid] = 0;
        if (tid < GMAX) g_done[tid] = 0;
        __syncthreads();
        for (int j = tid; j < G; j += TPB) g_flags[gtl[j]] = 1;
    }
}

// -------- kA80: fused logit + sumL1 (C==80 fast path) --------
__global__ void __launch_bounds__(TPB) kA80(const float* __restrict__ ps, int N) {
    __shared__ float s[32 * 81];
    __shared__ float part[8][33];
    int tid = threadIdx.x;
    int n0 = blockIdx.x * 32;
    int rows = min(32, N - n0);
    for (int i = tid; i < rows * 80; i += TPB) {
        int r = i / 80, c = i - r * 80;
        s[r * 81 + c] = ps[(size_t)n0 * 80 + i];
    }
    __syncthreads();
    int lane = tid & 31, w = tid >> 5;
    int n = n0 + lane;
    if (lane < rows) {
        float prod0 = 1.f, prod1 = 1.f;
        #pragma unroll
        for (int j = 0; j < 10; j++) {
            int c = w + j * 8;
            float p = s[lane * 81 + c];
            float q = 1.f - p;
            if (j < 5) prod0 *= q; else prod1 *= q;
            if (g_flags[c])
                g_D[(size_t)c * N + n] = __logf(__fdividef(p, q));
        }
        part[w][lane] = __logf(prod0) + __logf(prod1);
    }
    __syncthreads();
    if (w == 0 && lane < rows) {
        float ssum = 0.f;
        #pragma unroll
        for (int k = 0; k < 8; k++) ssum += part[k][lane];
        g_sumL1[n] = ssum;
    }
}

// generic fallback
__global__ void kAgen(const float* __restrict__ ps, int N, int C) {
    int n = blockIdx.x * blockDim.x + threadIdx.x;
    if (n >= N) return;
    float ssum = 0.f;
    for (int c = 0; c < C; c++) {
        float p = ps[(size_t)n * C + c];
        float L  = fmaxf(__logf(p), -100.f);
        float L1 = fmaxf(__logf(1.f - p), -100.f);
        g_D[(size_t)c * N + n] = L - L1;
        ssum += L1;
    }
    g_sumL1[n] = ssum;
}

// -------- kB: pairwise IoU + cost, single float2 store per pair --------
__global__ void __launch_bounds__(TPB) kB(
    const float* __restrict__ priors, const float* __restrict__ dec,
    const float* __restrict__ gtb, const int* __restrict__ gtl,
    int N, int G)
{
    __shared__ float4 sg0[GTILE];
    __shared__ float4 sg1[GTILE];
    int tid = threadIdx.x;
    int g0 = blockIdx.y * GTILE;
    int gcnt = min(GTILE, G - g0);
    if (tid < gcnt) {
        int g = g0 + tid;
        float x0 = gtb[4*g+0], y0 = gtb[4*g+1], x1 = gtb[4*g+2], y1 = gtb[4*g+3];
        sg0[tid] = make_float4(x0, y0, x1, y1);
        float gcx = (x0 + x1) * 0.5f, gcy = (y0 + y1) * 0.5f;
        float area = fmaxf(x1 - x0, 0.f) * fmaxf(y1 - y0, 0.f);
        sg1[tid] = make_float4(gcx, gcy, area, __int_as_float(gtl[g]));
    }
    __syncthreads();

    int n = blockIdx.x * blockDim.x + tid;
    if (n >= N) return;
    float4 pq = ((const float4*)priors)[n];
    float px = pq.x, py = pq.y;
    float a1 = px + CRAD * pq.z, a2 = px - CRAD * pq.z;
    float b1 = py + CRAD * pq.w, b2 = py - CRAD * pq.w;
    float4 dq = ((const float4*)dec)[n];
    float dx0 = dq.x, dy0 = dq.y, dx1 = dq.z, dy1 = dq.w;
    float aa = fmaxf(dx1 - dx0, 0.f) * fmaxf(dy1 - dy0, 0.f);
    float sL1 = g_sumL1[n];

    bool vacc = false;
    #pragma unroll
    for (int gi = 0; gi < GTILE; gi++) {
        if (gi < gcnt) {
            float4 q0 = sg0[gi];
            float4 q1 = sg1[gi];
            int g = g0 + gi;
            float m1 = fminf(fminf(px - q0.x, py - q0.y), fminf(q0.z - px, q0.w - py));
            float m2 = fminf(fminf(a1 - q1.x, b1 - q1.y), fminf(q1.x - a2, q1.y - b2));
            bool ing = m1 > 0.f, inc = m2 > 0.f;
            vacc = vacc || ing || inc;
            float w = fmaxf(fminf(dx1, q0.z) - fmaxf(dx0, q0.x), 0.f);
            float h = fmaxf(fminf(dy1, q0.w) - fmaxf(dy0, q0.y), 0.f);
            float inter = w * h;
            float uni = fmaxf(aa + q1.z - inter, EPSF);
            float iou = __fdividef(inter, uni);
            int lbl = __float_as_int(q1.w);
            float cls = -g_D[(size_t)lbl * N + n] - sL1;
            float cost = cls - 3.0f * __logf(iou + EPSF);
            if (!(ing && inc)) cost += INF_F;
            g_ic[(size_t)g * N + n] = make_float2(iou, cost);
        }
    }
    unsigned m = __ballot_sync(__activemask(), vacc);
    if ((tid & 31) == 0 && m) atomicOr(&g_valid[n >> 5], m);
}

// build keys for one element; masked values: iou->0, cost->BIG
__device__ __forceinline__ void mkkeys(float io, float co, bool vd, int n,
                                       ull& keyi, ull& keyc) {
    float iov = vd ? io : 0.f;
    float cov = vd ? co : BIG_F;
    keyi = ((ull)(unsigned)~fkey(iov) << 32) | (unsigned)n;
    keyc = ((ull)fkey(cov) << 32) | (unsigned)n;
}

// -------- kTopPart: grid (G, SPLIT). sample-threshold exact top-10 of both
//          lists per slice; last block per g merges + dynamic_k + atomics ----
__global__ void __launch_bounds__(TPB) kTopPart(int N) {
    __shared__ ull  sbuf[2][CAP];
    __shared__ ull  ssamp[2][16];
    __shared__ ull  sT[2];
    __shared__ int  scnt[2];
    __shared__ ull  skeep[2][TK];
    __shared__ int  sfl, sdk;

    int g = blockIdx.x, s = blockIdx.y;
    int tid = threadIdx.x, lane = tid & 31, w = tid >> 5;
    int len = (((N + SPLIT - 1) / SPLIT) + 3) & ~3;
    int n0 = s * len;
    int n1 = min(N, n0 + len);
    int total = n1 - n0;
    int iters = total > 0 ? (total + TPB * 2 - 1) / (TPB * 2) : 0;
    const float2* col = g_ic + (size_t)g * N;

    if (tid < 2) scnt[tid] = 0;

    // ---------------- phase A: per-warp top-2 samples ----------------
    ull i1 = ~0ULL, i2 = ~0ULL, c1 = ~0ULL, c2 = ~0ULL;
    for (int it = 0; it < iters; it++) {
        int n = n0 + (it * TPB + tid) * 2;
        ull ki0 = ~0ULL, ki1 = ~0ULL, kc0 = ~0ULL, kc1 = ~0ULL;
        if (n + 1 < n1) {
            float4 v = *reinterpret_cast<const float4*>(col + n);
            unsigned wv = g_valid[n >> 5] >> (n & 31);
            mkkeys(v.x, v.y, wv & 1u, n, ki0, kc0);
            mkkeys(v.z, v.w, (wv >> 1) & 1u, n + 1, ki1, kc1);
        } else if (n < n1) {
            float2 p = col[n];
            bool vd = (g_valid[n >> 5] >> (n & 31)) & 1u;
            mkkeys(p.x, p.y, vd, n, ki0, kc0);
        }
        wtop2(i1, i2, ki0);
        wtop2(i1, i2, ki1);
        wtop2(c1, c2, kc0);
        wtop2(c1, c2, kc1);
    }
    if (lane == 0) {
        ssamp[0][2 * w] = i1; ssamp[0][2 * w + 1] = i2;
        ssamp[1][2 * w] = c1; ssamp[1][2 * w + 1] = c2;
    }
    __syncthreads();

    // ---------------- threshold: 10th smallest of 16 samples ----------------
    if (w < 2) {
        ull myk = (lane < 16) ? ssamp[w][lane] : ~0ULL;
        int cnt = 0;
        #pragma unroll
        for (int j = 0; j < 16; j++) {
            ull o = __shfl_sync(FULLM, myk, j);
            cnt += (o < myk) ? 1 : 0;
        }
        unsigned sel = __ballot_sync(FULLM, lane < 16 && cnt == 9 && myk != ~0ULL);
        ull T = ~0ULL;
        if (sel) {
            int l = __ffs(sel) - 1;
            T = __shfl_sync(FULLM, myk, l);
        } else {
            T = __shfl_sync(FULLM, myk, 0);  // dummy to keep shfl collective
            T = ~0ULL;
        }
        if (lane == 0) sT[w] = T;
    }
    __syncthreads();
    ull Ti = sT[0], Tc = sT[1];

    // ---------------- phase B: compaction ----------------
    for (int it = 0; it < iters; it++) {
        int n = n0 + (it * TPB + tid) * 2;
        ull ki0 = ~0ULL, ki1 = ~0ULL, kc0 = ~0ULL, kc1 = ~0ULL;
        if (n + 1 < n1) {
            float4 v = *reinterpret_cast<const float4*>(col + n);
            unsigned wv = g_valid[n >> 5] >> (n & 31);
            mkkeys(v.x, v.y, wv & 1u, n, ki0, kc0);
            mkkeys(v.z, v.w, (wv >> 1) & 1u, n + 1, ki1, kc1);
        } else if (n < n1) {
            float2 p = col[n];
            bool vd = (g_valid[n >> 5] >> (n & 31)) & 1u;
            mkkeys(p.x, p.y, vd, n, ki0, kc0);
        }
        if (ki0 <= Ti) { int p = atomicAdd(&scnt[0], 1); if (p < CAP) sbuf[0][p] = ki0; }
        if (ki1 <= Ti) { int p = atomicAdd(&scnt[0], 1); if (p < CAP) sbuf[0][p] = ki1; }
        if (kc0 <= Tc) { int p = atomicAdd(&scnt[1], 1); if (p < CAP) sbuf[1][p] = kc0; }
        if (kc1 <= Tc) { int p = atomicAdd(&scnt[1], 1); if (p < CAP) sbuf[1][p] = kc1; }
    }
    __syncthreads();

    // ---------------- exact top-10 extraction from buffers ----------------
    if (w < 2) {
        int cnt = min(scnt[w], CAP);
        ull* buf = sbuf[w];
        for (int r = 0; r < TK; r++) {
            ull m = ~0ULL;
            for (int i = lane; i < cnt; i += 32) m = umin64(m, buf[i]);
            #pragma unroll
            for (int off = 16; off; off >>= 1)
                m = umin64(m, __shfl_xor_sync(FULLM, m, off));
            for (int i = lane; i < cnt; i += 32)
                if (buf[i] == m) buf[i] = ~0ULL;
            if (lane == 0) skeep[w][r] = m;
        }
    }
    __syncthreads();
    if (w == 0 && lane < TK) g_piou [(g * SPLIT + s) * TK + lane] = skeep[0][lane];
    if (w == 1 && lane < TK) g_pcost[(g * SPLIT + s) * TK + lane] = skeep[1][lane];
    __syncthreads();
    if (tid == 0) {
        __threadfence();
        int old = atomicAdd(&g_done[g], 1);
        sfl = (old == gridDim.y - 1);
    }
    __syncthreads();
    if (!sfl) return;

    // ---------------- last block for g: merge 80 keys per list ----------------
    if (w < 2) {
        const ull* src = (w == 0) ? &g_piou[g * TOTK] : &g_pcost[g * TOTK];
        ull k0 = (lane      < TOTK) ? __ldcg(&src[lane])      : ~0ULL;
        ull k1 = (lane + 32 < TOTK) ? __ldcg(&src[lane + 32]) : ~0ULL;
        ull k2 = (lane + 64 < TOTK) ? __ldcg(&src[lane + 64]) : ~0ULL;
        for (int r = 0; r < TK; r++) {
            ull m = umin64(k0, umin64(k1, k2));
            #pragma unroll
            for (int off = 16; off; off >>= 1)
                m = umin64(m, __shfl_xor_sync(FULLM, m, off));
            if (k0 == m) k0 = ~0ULL;
            else if (k1 == m) k1 = ~0ULL;
            else if (k2 == m) k2 = ~0ULL;
            if (lane == 0) skeep[w][r] = m;
        }
    }
    __syncthreads();
    if (tid == 0) {
        float ssum = 0.f;
        #pragma unroll
        for (int r = 0; r < TK; r++) {
            ull k = skeep[0][r];
            if (k != ~0ULL) ssum += unfkey(~(unsigned)(k >> 32));
        }
        int dk = (int)ssum;
        sdk = dk < 1 ? 1 : (dk > TK ? TK : dk);
    }
    __syncthreads();
    if (tid < sdk) {
        ull k = skeep[1][tid];
        if (k != ~0ULL) {
            int n = (int)(unsigned)k;
            atomicAdd(&g_cnt[n], 1);
            atomicMin(&g_mg[n], g);
        }
    }
}

// -------- finalize --------
__global__ void kFinal(float* __restrict__ out, int N, int G) {
    int n = blockIdx.x * blockDim.x + threadIdx.x;
    if (n >= N) return;
    int c = g_cnt[n];
    bool val = (g_valid[n >> 5] >> (n & 31)) & 1u;
    float gi = 0.f, lb = -1.f, io = -INF_F;
    if (c == 1) {
        int g = g_mg[n];
        gi = (float)g; lb = 1.f;
        io = val ? g_ic[(size_t)g * N + n].x : 0.f;
    } else if (c > 1) {
        lb = 1.f;
        if (!val) { gi = 0.f; io = 0.f; }
        else {
            float best = 3.4e38f; int bg = 0;
            for (int g = 0; g < G; g++) {
                float v = g_ic[(size_t)g * N + n].y;
                if (v < best) { best = v; bg = g; }
            }
            gi = (float)bg;
            io = g_ic[(size_t)bg * N + n].x;
        }
    }
    out[n] = gi;
    out[N + n] = lb;
    out[2 * N + n] = io;
}

extern "C" void kernel_launch(void* const* d_in, const int* in_sizes, int n_in,
                              void* d_out, int out_size) {
    const float* ps  = (const float*)d_in[0];
    const float* pri = (const float*)d_in[1];
    const float* dec = (const float*)d_in[2];
    const float* gtb = (const float*)d_in[3];
    const int*   gtl = (const int*)d_in[4];
    int N = in_sizes[1] / 4;
    int G = in_sizes[3] / 4;
    int C = in_sizes[0] / N;
    if (N > NMAX || G > GMAX || C > CMAX) return;
    float* out = (float*)d_out;
    (void)out_size; (void)n_in;

    kSetup<<<(N + TPB - 1) / TPB, TPB>>>(gtl, N, G);
    if (C == 80)
        kA80<<<(N + 31) / 32, TPB>>>(ps, N);
    else
        kAgen<<<(N + TPB - 1) / TPB, TPB>>>(ps, N, C);
    dim3 gb((N + TPB - 1) / TPB, (G + GTILE - 1) / GTILE);
    kB<<<gb, TPB>>>(pri, dec, gtb, gtl, N, G);
    dim3 gt(G, SPLIT);
    kTopPart<<<gt, TPB>>>(N);
    kFinal<<<(N + TPB - 1) / TPB, TPB>>>(out, N, G);
}

// round 7
// speedup vs baseline: 4.3752x; 1.4471x over previous
#include <cuda_runtime.h>
#include <stdint.h>

#define NMAX 33600
#define GMAX 128
#define CMAX 80
#define TPB 256
#define TK 10
#define GTILE 16
#define SPLIT 8
#define NW (TPB / 32)
#define CAP 768
#define TOTK (SPLIT * TK)               // 80 partial keys per gt per list
#define EPSF 1e-7f
#define INF_F 100000.0f
#define BIG_F 100000000.0f
#define CRAD 2.5f
#define NWORDS ((NMAX + 31) / 32)
#define FULLM 0xffffffffu

typedef unsigned long long ull;

// ---- scratch as __device__ globals (allocation-free rule) ----
__device__ float    g_D[(size_t)CMAX * NMAX];    // logit(p), class-major (used classes)
__device__ float    g_sumL1[NMAX];
__device__ float2   g_ic[(size_t)GMAX * NMAX];   // {iou, cost} gt-major
__device__ unsigned g_valid[NWORDS];
__device__ int      g_cnt[NMAX];
__device__ int      g_mg[NMAX];
__device__ int      g_flags[CMAX];
__device__ int      g_done[GMAX];
__device__ ull      g_piou [GMAX * TOTK];
__device__ ull      g_pcost[GMAX * TOTK];

// monotone float->uint (ascending order preserved)
__device__ __forceinline__ unsigned fkey(float f) {
    unsigned u = __float_as_uint(f);
    return (u & 0x80000000u) ? ~u : (u | 0x80000000u);
}
__device__ __forceinline__ float unfkey(unsigned k) {
    unsigned u = (k & 0x80000000u) ? (k ^ 0x80000000u) : ~k;
    return __uint_as_float(u);
}

__device__ __forceinline__ ull umin64(ull a, ull b) { return a < b ? a : b; }

// -------- kSetup --------
__global__ void kSetup(const int* __restrict__ gtl, int N, int G) {
    int tid = threadIdx.x;
    int i = blockIdx.x * blockDim.x + tid;
    if (i < N) { g_cnt[i] = 0; g_mg[i] = 0x7fffffff; }
    if (i < NWORDS) g_valid[i] = 0u;
    if (blockIdx.x == 0) {
        if (tid < CMAX) g_flags[tid] = 0;
        if (tid < GMAX) g_done[tid] = 0;
        __syncthreads();
        for (int j = tid; j < G; j += TPB) g_flags[gtl[j]] = 1;
    }
}

// -------- kA80: fused logit + sumL1 (C==80 fast path) --------
__global__ void __launch_bounds__(TPB) kA80(const float* __restrict__ ps, int N) {
    __shared__ float s[32 * 81];
    __shared__ float part[8][33];
    int tid = threadIdx.x;
    int n0 = blockIdx.x * 32;
    int rows = min(32, N - n0);
    for (int i = tid; i < rows * 80; i += TPB) {
        int r = i / 80, c = i - r * 80;
        s[r * 81 + c] = ps[(size_t)n0 * 80 + i];
    }
    __syncthreads();
    int lane = tid & 31, w = tid >> 5;
    int n = n0 + lane;
    if (lane < rows) {
        float prod0 = 1.f, prod1 = 1.f;
        #pragma unroll
        for (int j = 0; j < 10; j++) {
            int c = w + j * 8;
            float p = s[lane * 81 + c];
            float q = 1.f - p;
            if (j < 5) prod0 *= q; else prod1 *= q;
            if (g_flags[c])
                g_D[(size_t)c * N + n] = __logf(__fdividef(p, q));
        }
        part[w][lane] = __logf(prod0) + __logf(prod1);
    }
    __syncthreads();
    if (w == 0 && lane < rows) {
        float ssum = 0.f;
        #pragma unroll
        for (int k = 0; k < 8; k++) ssum += part[k][lane];
        g_sumL1[n] = ssum;
    }
}

// generic fallback
__global__ void kAgen(const float* __restrict__ ps, int N, int C) {
    int n = blockIdx.x * blockDim.x + threadIdx.x;
    if (n >= N) return;
    float ssum = 0.f;
    for (int c = 0; c < C; c++) {
        float p = ps[(size_t)n * C + c];
        float L  = fmaxf(__logf(p), -100.f);
        float L1 = fmaxf(__logf(1.f - p), -100.f);
        g_D[(size_t)c * N + n] = L - L1;
        ssum += L1;
    }
    g_sumL1[n] = ssum;
}

// -------- kB: pairwise IoU + cost, single float2 store per pair --------
__global__ void __launch_bounds__(TPB) kB(
    const float* __restrict__ priors, const float* __restrict__ dec,
    const float* __restrict__ gtb, const int* __restrict__ gtl,
    int N, int G)
{
    __shared__ float4 sg0[GTILE];
    __shared__ float4 sg1[GTILE];
    int tid = threadIdx.x;
    int g0 = blockIdx.y * GTILE;
    int gcnt = min(GTILE, G - g0);
    if (tid < gcnt) {
        int g = g0 + tid;
        float x0 = gtb[4*g+0], y0 = gtb[4*g+1], x1 = gtb[4*g+2], y1 = gtb[4*g+3];
        sg0[tid] = make_float4(x0, y0, x1, y1);
        float gcx = (x0 + x1) * 0.5f, gcy = (y0 + y1) * 0.5f;
        float area = fmaxf(x1 - x0, 0.f) * fmaxf(y1 - y0, 0.f);
        sg1[tid] = make_float4(gcx, gcy, area, __int_as_float(gtl[g]));
    }
    __syncthreads();

    int n = blockIdx.x * blockDim.x + tid;
    if (n >= N) return;
    float4 pq = ((const float4*)priors)[n];
    float px = pq.x, py = pq.y;
    float a1 = px + CRAD * pq.z, a2 = px - CRAD * pq.z;
    float b1 = py + CRAD * pq.w, b2 = py - CRAD * pq.w;
    float4 dq = ((const float4*)dec)[n];
    float dx0 = dq.x, dy0 = dq.y, dx1 = dq.z, dy1 = dq.w;
    float aa = fmaxf(dx1 - dx0, 0.f) * fmaxf(dy1 - dy0, 0.f);
    float sL1 = g_sumL1[n];

    bool vacc = false;
    #pragma unroll
    for (int gi = 0; gi < GTILE; gi++) {
        if (gi < gcnt) {
            float4 q0 = sg0[gi];
            float4 q1 = sg1[gi];
            int g = g0 + gi;
            float m1 = fminf(fminf(px - q0.x, py - q0.y), fminf(q0.z - px, q0.w - py));
            float m2 = fminf(fminf(a1 - q1.x, b1 - q1.y), fminf(q1.x - a2, q1.y - b2));
            bool ing = m1 > 0.f, inc = m2 > 0.f;
            vacc = vacc || ing || inc;
            float w = fmaxf(fminf(dx1, q0.z) - fmaxf(dx0, q0.x), 0.f);
            float h = fmaxf(fminf(dy1, q0.w) - fmaxf(dy0, q0.y), 0.f);
            float inter = w * h;
            float uni = fmaxf(aa + q1.z - inter, EPSF);
            float iou = __fdividef(inter, uni);
            int lbl = __float_as_int(q1.w);
            float cls = -g_D[(size_t)lbl * N + n] - sL1;
            float cost = cls - 3.0f * __logf(iou + EPSF);
            if (!(ing && inc)) cost += INF_F;
            g_ic[(size_t)g * N + n] = make_float2(iou, cost);
        }
    }
    unsigned m = __ballot_sync(__activemask(), vacc);
    if ((tid & 31) == 0 && m) atomicOr(&g_valid[n >> 5], m);
}

// -------- kTopPart: grid (G, SPLIT). float-threshold sampling + compaction.
//          Last block per g merges + dynamic_k + atomics. ----
__global__ void __launch_bounds__(TPB) kTopPart(int N) {
    __shared__ ull   sbuf[2][CAP];
    __shared__ float ssamp[2][16];
    __shared__ float sT[2];
    __shared__ int   scnt[2];
    __shared__ ull   skeep[2][TK];
    __shared__ int   sfl, sdk;

    int g = blockIdx.x, s = blockIdx.y;
    int tid = threadIdx.x, lane = tid & 31, w = tid >> 5;
    int len = (((N + SPLIT - 1) / SPLIT) + 3) & ~3;
    int n0 = s * len;
    int n1 = min(N, n0 + len);
    const float2* col = g_ic + (size_t)g * N;

    if (tid < 2) scnt[tid] = 0;

    // ---------------- phase A: per-thread float top-2, cheap scan ----------------
    float i1 = -1.f, i2 = -1.f;          // two largest masked ious
    float c1 = 3.0e38f, c2 = 3.0e38f;    // two smallest masked costs
    int nfull = n0 + (((n1 - n0) / 4) * 4);
    for (int n = n0 + tid * 4; n < nfull; n += TPB * 4) {
        float4 v0 = *reinterpret_cast<const float4*>(col + n);
        float4 v1 = *reinterpret_cast<const float4*>(col + n + 2);
        unsigned wv = g_valid[n >> 5] >> (n & 31);
        float io[4] = { (wv & 1u) ? v0.x : 0.f, (wv & 2u) ? v0.z : 0.f,
                        (wv & 4u) ? v1.x : 0.f, (wv & 8u) ? v1.z : 0.f };
        float co[4] = { (wv & 1u) ? v0.y : BIG_F, (wv & 2u) ? v0.w : BIG_F,
                        (wv & 4u) ? v1.y : BIG_F, (wv & 8u) ? v1.w : BIG_F };
        #pragma unroll
        for (int k = 0; k < 4; k++) {
            if (io[k] > i2) { if (io[k] > i1) { i2 = i1; i1 = io[k]; } else i2 = io[k]; }
            if (co[k] < c2) { if (co[k] < c1) { c2 = c1; c1 = co[k]; } else c2 = co[k]; }
        }
    }
    for (int n = nfull + tid; n < n1; n += TPB) {
        float2 p = col[n];
        bool vd = (g_valid[n >> 5] >> (n & 31)) & 1u;
        float io = vd ? p.x : 0.f;
        float co = vd ? p.y : BIG_F;
        if (io > i2) { if (io > i1) { i2 = i1; i1 = io; } else i2 = io; }
        if (co < c2) { if (co < c1) { c2 = c1; c1 = co; } else c2 = co; }
    }
    // warp-merge top-2 (once)
    #pragma unroll
    for (int off = 16; off; off >>= 1) {
        float oi1 = __shfl_xor_sync(FULLM, i1, off);
        float oi2 = __shfl_xor_sync(FULLM, i2, off);
        float ni1 = fmaxf(i1, oi1);
        float ni2 = fmaxf(fminf(i1, oi1), fmaxf(i2, oi2));
        i1 = ni1; i2 = ni2;
        float oc1 = __shfl_xor_sync(FULLM, c1, off);
        float oc2 = __shfl_xor_sync(FULLM, c2, off);
        float nc1 = fminf(c1, oc1);
        float nc2 = fminf(fmaxf(c1, oc1), fminf(c2, oc2));
        c1 = nc1; c2 = nc2;
    }
    if (lane == 0) {
        ssamp[0][2 * w] = i1; ssamp[0][2 * w + 1] = i2;
        ssamp[1][2 * w] = c1; ssamp[1][2 * w + 1] = c2;
    }
    __syncthreads();

    // ---------------- threshold: 10th best of 16 samples (ties via lane) --------
    if (w < 2) {
        float v = (lane < 16) ? ssamp[w][lane] : (w ? 3.0e38f : -1.f);
        int cnt = 0;
        #pragma unroll
        for (int j = 0; j < 16; j++) {
            float o = __shfl_sync(FULLM, v, j);
            bool better = (w == 0) ? (o > v) : (o < v);
            cnt += (better || (o == v && j < lane)) ? 1 : 0;
        }
        unsigned sel = __ballot_sync(FULLM, lane < 16 && cnt == 9);
        int l = __ffs(sel) - 1;
        float T = __shfl_sync(FULLM, v, l);
        if (lane == 0) sT[w] = T;
    }
    __syncthreads();
    float Ti = sT[0], Tc = sT[1];

    // ---------------- phase B: compaction (float compares, keys on hit) --------
    for (int n = n0 + tid * 4; n < nfull; n += TPB * 4) {
        float4 v0 = *reinterpret_cast<const float4*>(col + n);
        float4 v1 = *reinterpret_cast<const float4*>(col + n + 2);
        unsigned wv = g_valid[n >> 5] >> (n & 31);
        float io[4] = { (wv & 1u) ? v0.x : 0.f, (wv & 2u) ? v0.z : 0.f,
                        (wv & 4u) ? v1.x : 0.f, (wv & 8u) ? v1.z : 0.f };
        float co[4] = { (wv & 1u) ? v0.y : BIG_F, (wv & 2u) ? v0.w : BIG_F,
                        (wv & 4u) ? v1.y : BIG_F, (wv & 8u) ? v1.w : BIG_F };
        #pragma unroll
        for (int k = 0; k < 4; k++) {
            int ni = n + k;
            if (io[k] >= Ti) {
                ull key = ((ull)(unsigned)~fkey(io[k]) << 32) | (unsigned)ni;
                int p = atomicAdd(&scnt[0], 1); if (p < CAP) sbuf[0][p] = key;
            }
            if (co[k] <= Tc) {
                ull key = ((ull)fkey(co[k]) << 32) | (unsigned)ni;
                int p = atomicAdd(&scnt[1], 1); if (p < CAP) sbuf[1][p] = key;
            }
        }
    }
    for (int n = nfull + tid; n < n1; n += TPB) {
        float2 p = col[n];
        bool vd = (g_valid[n >> 5] >> (n & 31)) & 1u;
        float io = vd ? p.x : 0.f;
        float co = vd ? p.y : BIG_F;
        if (io >= Ti) {
            ull key = ((ull)(unsigned)~fkey(io) << 32) | (unsigned)n;
            int q = atomicAdd(&scnt[0], 1); if (q < CAP) sbuf[0][q] = key;
        }
        if (co <= Tc) {
            ull key = ((ull)fkey(co) << 32) | (unsigned)n;
            int q = atomicAdd(&scnt[1], 1); if (q < CAP) sbuf[1][q] = key;
        }
    }
    __syncthreads();

    // ---------------- exact top-10 extraction from buffers ----------------
    if (w < 2) {
        int cnt = min(scnt[w], CAP);
        ull* buf = sbuf[w];
        for (int r = 0; r < TK; r++) {
            ull m = ~0ULL;
            for (int i = lane; i < cnt; i += 32) m = umin64(m, buf[i]);
            #pragma unroll
            for (int off = 16; off; off >>= 1)
                m = umin64(m, __shfl_xor_sync(FULLM, m, off));
            for (int i = lane; i < cnt; i += 32)
                if (buf[i] == m) buf[i] = ~0ULL;
            if (lane == 0) skeep[w][r] = m;
        }
    }
    __syncthreads();
    if (w == 0 && lane < TK) g_piou [(g * SPLIT + s) * TK + lane] = skeep[0][lane];
    if (w == 1 && lane < TK) g_pcost[(g * SPLIT + s) * TK + lane] = skeep[1][lane];
    __syncthreads();
    if (tid == 0) {
        __threadfence();
        int old = atomicAdd(&g_done[g], 1);
        sfl = (old == gridDim.y - 1);
    }
    __syncthreads();
    if (!sfl) return;

    // ---------------- last block for g: merge 80 keys per list ----------------
    if (w < 2) {
        const ull* src = (w == 0) ? &g_piou[g * TOTK] : &g_pcost[g * TOTK];
        ull k0 = (lane      < TOTK) ? __ldcg(&src[lane])      : ~0ULL;
        ull k1 = (lane + 32 < TOTK) ? __ldcg(&src[lane + 32]) : ~0ULL;
        ull k2 = (lane + 64 < TOTK) ? __ldcg(&src[lane + 64]) : ~0ULL;
        for (int r = 0; r < TK; r++) {
            ull m = umin64(k0, umin64(k1, k2));
            #pragma unroll
            for (int off = 16; off; off >>= 1)
                m = umin64(m, __shfl_xor_sync(FULLM, m, off));
            if (k0 == m) k0 = ~0ULL;
            else if (k1 == m) k1 = ~0ULL;
            else if (k2 == m) k2 = ~0ULL;
            if (lane == 0) skeep[w][r] = m;
        }
    }
    __syncthreads();
    if (tid == 0) {
        float ssum = 0.f;
        #pragma unroll
        for (int r = 0; r < TK; r++) {
            ull k = skeep[0][r];
            if (k != ~0ULL) ssum += unfkey(~(unsigned)(k >> 32));
        }
        int dk = (int)ssum;
        sdk = dk < 1 ? 1 : (dk > TK ? TK : dk);
    }
    __syncthreads();
    if (tid < sdk) {
        ull k = skeep[1][tid];
        if (k != ~0ULL) {
            int n = (int)(unsigned)k;
            atomicAdd(&g_cnt[n], 1);
            atomicMin(&g_mg[n], g);
        }
    }
}

// -------- finalize --------
__global__ void kFinal(float* __restrict__ out, int N, int G) {
    int n = blockIdx.x * blockDim.x + threadIdx.x;
    if (n >= N) return;
    int c = g_cnt[n];
    bool val = (g_valid[n >> 5] >> (n & 31)) & 1u;
    float gi = 0.f, lb = -1.f, io = -INF_F;
    if (c == 1) {
        int g = g_mg[n];
        gi = (float)g; lb = 1.f;
        io = val ? g_ic[(size_t)g * N + n].x : 0.f;
    } else if (c > 1) {
        lb = 1.f;
        if (!val) { gi = 0.f; io = 0.f; }
        else {
            float best = 3.4e38f; int bg = 0;
            for (int g = 0; g < G; g++) {
                float v = g_ic[(size_t)g * N + n].y;
                if (v < best) { best = v; bg = g; }
            }
            gi = (float)bg;
            io = g_ic[(size_t)bg * N + n].x;
        }
    }
    out[n] = gi;
    out[N + n] = lb;
    out[2 * N + n] = io;
}

extern "C" void kernel_launch(void* const* d_in, const int* in_sizes, int n_in,
                              void* d_out, int out_size) {
    const float* ps  = (const float*)d_in[0];
    const float* pri = (const float*)d_in[1];
    const float* dec = (const float*)d_in[2];
    const float* gtb = (const float*)d_in[3];
    const int*   gtl = (const int*)d_in[4];
    int N = in_sizes[1] / 4;
    int G = in_sizes[3] / 4;
    int C = in_sizes[0] / N;
    if (N > NMAX || G > GMAX || C > CMAX) return;
    float* out = (float*)d_out;
    (void)out_size; (void)n_in;

    kSetup<<<(N + TPB - 1) / TPB, TPB>>>(gtl, N, G);
    if (C == 80)
        kA80<<<(N + 31) / 32, TPB>>>(ps, N);
    else
        kAgen<<<(N + TPB - 1) / TPB, TPB>>>(ps, N, C);
    dim3 gb((N + TPB - 1) / TPB, (G + GTILE - 1) / GTILE);
    kB<<<gb, TPB>>>(pri, dec, gtb, gtl, N, G);
    dim3 gt(G, SPLIT);
    kTopPart<<<gt, TPB>>>(N);
    kFinal<<<(N + TPB - 1) / TPB, TPB>>>(out, N, G);
}